// round 4
// baseline (speedup 1.0000x reference)
#include <cuda_runtime.h>
#include <cstdint>

#define IN_DIM    4096
#define OUT_DIM   1024
#define NROWS     16384
#define NCHUNK    8
#define CHUNK     512            // columns per shared chunk
#define PITCH     33             // floats per column row in shared (odd -> conflict-free)
#define PLANE     (CHUNK * PITCH)       // 16896 floats per 32-n plane
#define SMEM_X_FLOATS (2 * PLANE)       // two planes: n 0..31 and n 32..63
#define ENTBUF_CAP 512
#define NWARPS    16
#define SMEM_BYTES (SMEM_X_FLOATS * 4 + NWARPS * ENTBUF_CAP * 4)   // 135168 + 32768 = 167936
#define SCALE     0.3162277660168379f   // 1/sqrt(10)

// Precomputed sparse structure (rebuilt every launch; deterministic).
// Entry encoding: low 31 bits = c_local * PITCH (float index into a chunk plane),
// bit 31 = sign (1 -> negate).
__device__ unsigned int g_ent[40960];
__device__ int g_cnt[NCHUNK * OUT_DIM];
__device__ int g_off[NCHUNK * OUT_DIM + 1];

// ---------------------------------------------------------------------------
// Prep 1: count nonzeros per (chunk, output-row) cell. One warp per row.
__global__ void jl_count(const float* __restrict__ Phi) {
    int w = threadIdx.x >> 5, lane = threadIdx.x & 31;
    int r = blockIdx.x * 8 + w;
    const float* row = Phi + (size_t)r * IN_DIM;
    #pragma unroll
    for (int ch = 0; ch < NCHUNK; ++ch) {
        int c = 0;
        for (int b = 0; b < CHUNK; b += 32) {
            float v = row[ch * CHUNK + b + lane];
            unsigned m = __ballot_sync(0xffffffffu, v != 0.0f);
            c += __popc(m);
        }
        if (lane == 0) g_cnt[ch * OUT_DIM + r] = c;
    }
}

// ---------------------------------------------------------------------------
// Prep 2: exclusive scan over the 8192 cell counts (chunk-major order).
__global__ void jl_scan() {
    __shared__ int sh[1024];
    int t = threadIdx.x;
    int loc[8];
    int s = 0;
    #pragma unroll
    for (int q = 0; q < 8; ++q) { loc[q] = s; s += g_cnt[t * 8 + q]; }
    sh[t] = s;
    __syncthreads();
    for (int d = 1; d < 1024; d <<= 1) {
        int v = 0;
        if (t >= d) v = sh[t - d];
        __syncthreads();
        sh[t] += v;
        __syncthreads();
    }
    int ex = (t == 0) ? 0 : sh[t - 1];
    #pragma unroll
    for (int q = 0; q < 8; ++q) g_off[t * 8 + q] = ex + loc[q];
    if (t == 1023) g_off[NCHUNK * OUT_DIM] = sh[1023];
}

// ---------------------------------------------------------------------------
// Prep 3: fill compact chunk-major entry array (ballot/popc compaction,
// deterministic, entries sorted by c within each cell).
__global__ void jl_fill(const float* __restrict__ Phi) {
    int w = threadIdx.x >> 5, lane = threadIdx.x & 31;
    int r = blockIdx.x * 8 + w;
    const float* row = Phi + (size_t)r * IN_DIM;
    unsigned lmask = (1u << lane) - 1u;
    for (int ch = 0; ch < NCHUNK; ++ch) {
        int pos = g_off[ch * OUT_DIM + r];
        for (int b = 0; b < CHUNK; b += 32) {
            float v = row[ch * CHUNK + b + lane];
            bool nz = (v != 0.0f);
            unsigned m = __ballot_sync(0xffffffffu, nz);
            if (nz) {
                int idx = pos + __popc(m & lmask);
                unsigned cl = (unsigned)(b + lane);  // c within chunk, 0..511
                g_ent[idx] = cl * PITCH + (v < 0.0f ? 0x80000000u : 0u);
            }
            pos += __popc(m);
        }
    }
}

// ---------------------------------------------------------------------------
// Main: block = 512 thr (16 warps). Block owns 64 x-rows x 512 output rows
// (blockIdx bit0 = which r-half; pairs of blocks share the same x strip so L2
// absorbs the duplicate read). Warp owns 32 output rows, float2 accumulators
// (n = lane and n = lane+32). x chunk lives in shared as two planes
// [512c][pitch 33] -> conflict-free stores and gathers.
__global__ __launch_bounds__(512, 1) void jl_main(const float* __restrict__ x,
                                                  float* __restrict__ out) {
    extern __shared__ float xs[];
    unsigned* entbuf = (unsigned*)(xs + SMEM_X_FLOATS);
    int tid  = threadIdx.x;
    int lane = tid & 31, w = tid >> 5;
    int ntile = blockIdx.x >> 1, rhalf = blockIdx.x & 1;
    int n0 = ntile * 64;
    int rbase = rhalf * 512 + w * 32;
    unsigned* eb = entbuf + w * ENTBUF_CAP;

    float2 acc[32];
    #pragma unroll
    for (int i = 0; i < 32; ++i) { acc[i].x = 0.0f; acc[i].y = 0.0f; }

    for (int ch = 0; ch < NCHUNK; ++ch) {
        // --- load x chunk: 512 cols x 64 rows, global coalesced, STS conflict-free
        const float* xg = x + (size_t)n0 * IN_DIM + ch * CHUNK + tid;
        #pragma unroll 16
        for (int k = 0; k < 64; ++k) {
            float v = xg[(size_t)k * IN_DIM];
            xs[(k >> 5) * PLANE + tid * PITCH + (k & 31)] = v;
        }

        // --- per-lane segment offsets for this warp's 32 output rows
        int o1 = g_off[ch * OUT_DIM + rbase + lane];
        int o2 = g_off[ch * OUT_DIM + rbase + lane + 1];
        int S = __shfl_sync(0xffffffffu, o1, 0);
        int E = __shfl_sync(0xffffffffu, o2, 31);

        // --- stage this warp's entry span into shared (warp-private, no sync needed)
        for (int k = S + lane; k < E; k += 32) {
            int d = k - S;
            if (d < ENTBUF_CAP) eb[d] = g_ent[k];
        }
        __syncthreads();

        // --- gather + signed accumulate
        #pragma unroll
        for (int i = 0; i < 32; ++i) {
            int b = __shfl_sync(0xffffffffu, o1, i) - S;
            int e = __shfl_sync(0xffffffffu, o2, i) - S;
            for (int j = b; j < e; ++j) {
                unsigned t  = eb[j];                 // uniform broadcast LDS
                unsigned fi = t & 0x7fffffffu;       // c_local * PITCH
                float v0 = xs[fi + lane];            // n = lane
                float v1 = xs[fi + lane + PLANE];    // n = lane + 32
                unsigned sg = t & 0x80000000u;
                acc[i].x += __int_as_float(__float_as_int(v0) ^ sg);
                acc[i].y += __int_as_float(__float_as_int(v1) ^ sg);
            }
        }
        __syncthreads();   // before next chunk overwrites xs
    }

    // --- epilogue: transpose through shared for coalesced global stores
    float* ob = xs;   // reuse as [512 r][pitch 65]
    #pragma unroll
    for (int i = 0; i < 32; ++i) {
        int rl = w * 32 + i;
        ob[rl * 65 + lane]      = acc[i].x * SCALE;   // n = lane
        ob[rl * 65 + 32 + lane] = acc[i].y * SCALE;   // n = lane + 32
    }
    __syncthreads();
    #pragma unroll 8
    for (int k = 0; k < 64; ++k) {
        out[(size_t)(n0 + k) * OUT_DIM + rhalf * 512 + tid] = ob[tid * 65 + k];
    }
}

// ---------------------------------------------------------------------------
extern "C" void kernel_launch(void* const* d_in, const int* in_sizes, int n_in,
                              void* d_out, int out_size) {
    const float* x   = (const float*)d_in[0];
    const float* Phi = (const float*)d_in[1];
    float* out = (float*)d_out;

    cudaFuncSetAttribute(jl_main, cudaFuncAttributeMaxDynamicSharedMemorySize,
                         SMEM_BYTES);

    jl_count<<<128, 256>>>(Phi);
    jl_scan<<<1, 1024>>>();
    jl_fill<<<128, 256>>>(Phi);
    jl_main<<<512, 512, SMEM_BYTES>>>(x, out);
}